// round 16
// baseline (speedup 1.0000x reference)
#include <cuda_runtime.h>
#include <cuda_fp16.h>
#include <math.h>
#include <stdint.h>

// ---------------------------------------------------------------------------
#define BATCH   8
#define SEQT    150
#define MTOT    1200
#define DIMC    1024
#define DINC    2048
#define DSTATE  16
#define DTRANK  64
#define XDBLC   96
#define INNERC  4096
#define MLPC    4096
#define DEPTHC  5
#define XKS     8
#define SKR     4

// ---------------------------------------------------------------------------
// Scratch
// ---------------------------------------------------------------------------
__device__ __half g_normh [MTOT * DIMC];
__device__ __half g_xzh   [MTOT * 2 * DINC];
__device__ __half g_xch   [MTOT * DINC];
__device__ float  g_xdbl  [MTOT * XDBLC];
__device__ __half g_xdbl16[MTOT * XDBLC];
__device__ float  g_xpart [XKS * MTOT * XDBLC];
__device__ __half g_dth   [MTOT * DINC];
__device__ __half g_yh    [MTOT * DINC];
__device__ __half g_qkvh  [MTOT * 3 * INNERC];
__device__ __half g_attnh [MTOT * INNERC];
__device__ __half g_ffnh  [MTOT * MLPC];
__device__ __half g_part2 [SKR * MTOT * DIMC];   // fp16 split-K partials

// fp16 weight copies (converted each launch; deterministic)
__device__ __half g_w_inproj[DEPTHC * 4096 * DIMC];
__device__ __half g_w_xproj [DEPTHC * XDBLC * DINC];
__device__ __half g_w_dt    [DEPTHC * DINC * DTRANK];
__device__ __half g_w_mamba [DEPTHC * DIMC * DINC];
__device__ __half g_w_qkv   [DEPTHC * 3 * INNERC * DIMC];
__device__ __half g_w_attn  [DEPTHC * DIMC * INNERC];
__device__ __half g_w_ffn1  [DEPTHC * MLPC * DIMC];
__device__ __half g_w_ffn2  [DEPTHC * DIMC * MLPC];

// ---------------------------------------------------------------------------
__device__ __forceinline__ float geluf(float x) {
    return 0.5f * x * (1.0f + erff(x * 0.70710678118654752f));
}
__device__ __forceinline__ float softplusf(float x) {
    return fmaxf(x, 0.0f) + log1pf(__expf(-fabsf(x)));
}
__device__ __forceinline__ float siluf(float x) {
    return x / (1.0f + __expf(-x));
}
__device__ __forceinline__ uint32_t ldh2(const __half* p) {
    return *reinterpret_cast<const uint32_t*>(p);
}
__device__ __forceinline__ void mma_f16(float c[4],
                                        uint32_t a0, uint32_t a1, uint32_t a2, uint32_t a3,
                                        uint32_t b0, uint32_t b1) {
    asm volatile(
        "mma.sync.aligned.m16n8k16.row.col.f32.f16.f16.f32 "
        "{%0,%1,%2,%3}, {%4,%5,%6,%7}, {%8,%9}, {%0,%1,%2,%3};"
        : "+f"(c[0]), "+f"(c[1]), "+f"(c[2]), "+f"(c[3])
        : "r"(a0), "r"(a1), "r"(a2), "r"(a3), "r"(b0), "r"(b1));
}
__device__ __forceinline__ void ldsm_x2_trans(uint32_t& b0, uint32_t& b1,
                                              uint32_t saddr) {
    asm volatile("ldmatrix.sync.aligned.m8n8.x2.trans.shared.b16 {%0,%1}, [%2];"
                 : "=r"(b0), "=r"(b1) : "r"(saddr));
}
__device__ __forceinline__ void cp16(uint32_t dst, const void* src, int sz) {
    asm volatile("cp.async.cg.shared.global [%0], [%1], 16, %2;"
                 :: "r"(dst), "l"(src), "r"(sz));
}
__device__ __forceinline__ uint32_t smem_u32(const void* p) {
    return (uint32_t)__cvta_generic_to_shared(p);
}

// ---------------------------------------------------------------------------
// fp32 -> fp16 bulk convert
// ---------------------------------------------------------------------------
__global__ void __launch_bounds__(256)
f32to16(const float* __restrict__ in, __half* __restrict__ out, int n4)
{
    const int i = blockIdx.x * 256 + threadIdx.x;
    if (i >= n4) return;
    const float4 v = reinterpret_cast<const float4*>(in)[i];
    __half2 h0 = __floats2half2_rn(v.x, v.y);
    __half2 h1 = __floats2half2_rn(v.z, v.w);
    uint2 o;
    o.x = *reinterpret_cast<uint32_t*>(&h0);
    o.y = *reinterpret_cast<uint32_t*>(&h1);
    reinterpret_cast<uint2*>(out)[i] = o;
}

// ---------------------------------------------------------------------------
// fp16 mma.sync GEMM.
// SK>1: blockIdx.z K-slice -> fp16 partials at C[z*M*N + m*ldc + n].
// EPI (SK==1): 1=fp16  2=gelu(+bias)->fp16  6=softplus(+bias)->fp16
// ---------------------------------------------------------------------------
template <int EPI, int SK, int BN>
__global__ void __launch_bounds__(256, 2)
gemm_h(const __half* __restrict__ A, int lda,
       const __half* __restrict__ B, int ldb,
       const float* __restrict__ bias,
       void* __restrict__ Cv, int ldc,
       int M, int N, int K)
{
    constexpr int PAD = 40;
    constexpr int NJ  = BN / 32;
    constexpr int BRQ = BN / 64;
    extern __shared__ __half smh[];
    __half* sA = smh;
    __half* sB = smh + 4 * 64 * PAD;

    const int m0    = blockIdx.y * 64;
    const int n0    = blockIdx.x * BN;
    const int Ks    = K / SK;
    const int kbase = (SK > 1) ? blockIdx.z * Ks : 0;
    const int tid   = threadIdx.x;
    const int lane  = tid & 31;
    const int warp  = tid >> 5;
    const int wm    = warp & 1;
    const int wn    = warp >> 1;
    const int g     = lane >> 2;
    const int ac    = lane & 3;
    const int NIT   = Ks >> 5;

    float acc[2][NJ][4];
#pragma unroll
    for (int i = 0; i < 2; i++)
#pragma unroll
        for (int j = 0; j < NJ; j++)
#pragma unroll
            for (int r = 0; r < 4; r++) acc[i][j][r] = 0.0f;

    auto issue = [&](int s, int k0, bool real) {
        if (real) {
            {
                const int row = tid >> 2;
                const int kq  = (tid & 3) * 8;
                cp16(smem_u32(&sA[(s * 64 + row) * PAD + kq]),
                     &A[(size_t)(m0 + row) * lda + kbase + k0 + kq],
                     (m0 + row < M) ? 16 : 0);
            }
#pragma unroll
            for (int r = 0; r < BRQ; r++) {
                const int idx = tid + r * 256;
                const int row = idx >> 2;
                const int kq  = (idx & 3) * 8;
                cp16(smem_u32(&sB[(s * BN + row) * PAD + kq]),
                     &B[(size_t)(n0 + row) * ldb + kbase + k0 + kq],
                     (n0 + row < N) ? 16 : 0);
            }
        }
        asm volatile("cp.async.commit_group;");
    };

    issue(0, 0, true);
    issue(1, 32, 1 < NIT);
    issue(2, 64, 2 < NIT);

    for (int it = 0; it < NIT; it++) {
        const int p = it & 3;
        asm volatile("cp.async.wait_group 2;");
        __syncthreads();
        issue((it + 3) & 3, (it + 3) << 5, (it + 3) < NIT);

        const __half* pa = &sA[p * 64 * PAD];
        const __half* pb = &sB[p * BN * PAD];
#pragma unroll
        for (int ks = 0; ks < 2; ks++) {
            const int kk = ks * 16;
            uint32_t af[2][4], bf[NJ][2];
#pragma unroll
            for (int i = 0; i < 2; i++) {
                const int r = wm * 32 + i * 16 + g;
                af[i][0] = ldh2(&pa[(r    ) * PAD + kk + ac * 2    ]);
                af[i][1] = ldh2(&pa[(r + 8) * PAD + kk + ac * 2    ]);
                af[i][2] = ldh2(&pa[(r    ) * PAD + kk + ac * 2 + 8]);
                af[i][3] = ldh2(&pa[(r + 8) * PAD + kk + ac * 2 + 8]);
            }
#pragma unroll
            for (int j = 0; j < NJ; j++) {
                const int c = wn * (8 * NJ) + j * 8 + g;
                bf[j][0] = ldh2(&pb[c * PAD + kk + ac * 2    ]);
                bf[j][1] = ldh2(&pb[c * PAD + kk + ac * 2 + 8]);
            }
#pragma unroll
            for (int i = 0; i < 2; i++)
#pragma unroll
                for (int j = 0; j < NJ; j++)
                    mma_f16(acc[i][j], af[i][0], af[i][1], af[i][2], af[i][3],
                            bf[j][0], bf[j][1]);
        }
        __syncthreads();
    }

    const size_t zoff = (SK > 1) ? (size_t)blockIdx.z * M * N : 0;
#pragma unroll
    for (int i = 0; i < 2; i++) {
#pragma unroll
        for (int j = 0; j < NJ; j++) {
            const int mb = m0 + wm * 32 + i * 16 + g;
            const int nb = n0 + wn * (8 * NJ) + j * 8 + ac * 2;
#pragma unroll
            for (int r2 = 0; r2 < 2; r2++) {
#pragma unroll
                for (int c2 = 0; c2 < 2; c2++) {
                    const int m = mb + r2 * 8;
                    const int n = nb + c2;
                    if (m >= M || n >= N) continue;
                    const size_t o = zoff + (size_t)m * ldc + n;
                    const float v = acc[i][j][r2 * 2 + c2];
                    if (SK > 1)        ((__half*)Cv)[o] = __float2half_rn(v);
                    else if (EPI == 1) ((__half*)Cv)[o] = __float2half_rn(v);
                    else if (EPI == 2) ((__half*)Cv)[o] = __float2half_rn(geluf(v + bias[n]));
                    else if (EPI == 6) ((__half*)Cv)[o] = __float2half_rn(softplusf(v + bias[n]));
                }
            }
        }
    }
}

// ---------------------------------------------------------------------------
// Fused split-K reduce (fp16 partials, fp32 sum) + residual + LayerNorm.
// ---------------------------------------------------------------------------
template <int EPI, bool DOLN>
__global__ void __launch_bounds__(256)
reduce_ln(const __half* __restrict__ part, const float* __restrict__ bias,
          float* __restrict__ X,
          const float* __restrict__ lnw, const float* __restrict__ lnb,
          __half* __restrict__ normh)
{
    const int row = blockIdx.x;
    const int tid = threadIdx.x;
    __shared__ float red[8];

    float v[4];
    float s = 0.f;
#pragma unroll
    for (int u = 0; u < 4; u++) {
        const int c = tid + u * 256;
        const size_t idx = (size_t)row * DIMC + c;
        float f = 0.f;
#pragma unroll
        for (int z = 0; z < SKR; z++)
            f += __half2float(part[idx + (size_t)z * MTOT * DIMC]);
        float nx;
        if (EPI == 3) nx = X[idx] + f + (bias ? bias[c] : 0.0f);
        else          nx = X[idx] + geluf(f + bias[c]);
        X[idx] = nx;
        v[u] = nx;
        s += nx;
    }
    if (!DOLN) return;

#pragma unroll
    for (int o = 16; o; o >>= 1) s += __shfl_xor_sync(0xffffffffu, s, o);
    if ((tid & 31) == 0) red[tid >> 5] = s;
    __syncthreads();
    float tot = 0.f;
#pragma unroll
    for (int u = 0; u < 8; u++) tot += red[u];
    const float mu = tot * (1.0f / 1024.0f);

    float s2 = 0.f;
#pragma unroll
    for (int u = 0; u < 4; u++) { const float d = v[u] - mu; s2 += d * d; }
    __syncthreads();
#pragma unroll
    for (int o = 16; o; o >>= 1) s2 += __shfl_xor_sync(0xffffffffu, s2, o);
    if ((tid & 31) == 0) red[tid >> 5] = s2;
    __syncthreads();
    float tot2 = 0.f;
#pragma unroll
    for (int u = 0; u < 8; u++) tot2 += red[u];
    const float rstd = rsqrtf(tot2 * (1.0f / 1024.0f) + 1e-5f);

    __half* orow = normh + (size_t)row * DIMC;
#pragma unroll
    for (int u = 0; u < 4; u++) {
        const int c = tid + u * 256;
        orow[c] = __float2half_rn((v[u] - mu) * rstd * lnw[c] + lnb[c]);
    }
}

// ---------------------------------------------------------------------------
__global__ void __launch_bounds__(256)
xproj_reduce(const float* __restrict__ part, float* __restrict__ C,
             __half* __restrict__ Ch)
{
    const int idx = blockIdx.x * 256 + threadIdx.x;
    if (idx >= MTOT * XDBLC) return;
    float s = 0.f;
#pragma unroll
    for (int ks = 0; ks < XKS; ks++)
        s += part[(size_t)ks * MTOT * XDBLC + idx];
    C[idx]  = s;
    Ch[idx] = __float2half_rn(s);
}

// ---------------------------------------------------------------------------
// x_proj split-K via gemm_h writes fp16 partials? No: keep fp32 (xpart is
// small, 3.7MB). Separate path: gemm_h SK>1 now writes fp16. So give xproj
// its own fp32 partial path by a tiny dedicated kernel variant flag.
// Simpler: reuse gemm_h fp16 partials for xproj too and reduce from fp16.
// ---------------------------------------------------------------------------
__global__ void __launch_bounds__(256)
xproj_reduce_h(const __half* __restrict__ part, float* __restrict__ C,
               __half* __restrict__ Ch)
{
    const int idx = blockIdx.x * 256 + threadIdx.x;
    if (idx >= MTOT * XDBLC) return;
    float s = 0.f;
#pragma unroll
    for (int ks = 0; ks < XKS; ks++)
        s += __half2float(part[(size_t)ks * MTOT * XDBLC + idx]);
    C[idx]  = s;
    Ch[idx] = __float2half_rn(s);
}

// ---------------------------------------------------------------------------
__global__ void __launch_bounds__(256)
ln_kernel(const float* __restrict__ x, const float* __restrict__ w,
          const float* __restrict__ b, __half* __restrict__ out)
{
    const int row = blockIdx.x;
    const int tid = threadIdx.x;
    const float* xr = x + (size_t)row * DIMC;
    __shared__ float red[8];

    float v[4];
    float s = 0.f;
#pragma unroll
    for (int u = 0; u < 4; u++) { v[u] = xr[tid + u * 256]; s += v[u]; }
#pragma unroll
    for (int o = 16; o; o >>= 1) s += __shfl_xor_sync(0xffffffffu, s, o);
    if ((tid & 31) == 0) red[tid >> 5] = s;
    __syncthreads();
    float tot = 0.f;
#pragma unroll
    for (int u = 0; u < 8; u++) tot += red[u];
    const float mu = tot * (1.0f / 1024.0f);

    float s2 = 0.f;
#pragma unroll
    for (int u = 0; u < 4; u++) { const float d = v[u] - mu; s2 += d * d; }
    __syncthreads();
#pragma unroll
    for (int o = 16; o; o >>= 1) s2 += __shfl_xor_sync(0xffffffffu, s2, o);
    if ((tid & 31) == 0) red[tid >> 5] = s2;
    __syncthreads();
    float tot2 = 0.f;
#pragma unroll
    for (int u = 0; u < 8; u++) tot2 += red[u];
    const float rstd = rsqrtf(tot2 * (1.0f / 1024.0f) + 1e-5f);

    __half* orow = out + (size_t)row * DIMC;
#pragma unroll
    for (int u = 0; u < 4; u++) {
        const int c = tid + u * 256;
        orow[c] = __float2half_rn((v[u] - mu) * rstd * w[c] + b[c]);
    }
}

// ---------------------------------------------------------------------------
// Depthwise causal conv on fp16 xz -> fp16 xch only
// ---------------------------------------------------------------------------
__global__ void __launch_bounds__(256)
conv_kernel(const __half* __restrict__ xz, const float* __restrict__ cw,
            const float* __restrict__ cb, __half* __restrict__ outh)
{
    const int m = blockIdx.x;
    const int d = blockIdx.y * 256 + threadIdx.x;
    const int b = m / SEQT, t = m % SEQT;
    float acc = cb[d];
#pragma unroll
    for (int j = 0; j < 4; j++) {
        const int tt = t + j - 3;
        if (tt >= 0)
            acc = fmaf(cw[d * 4 + j],
                       __half2float(xz[((size_t)(b * SEQT + tt)) * 4096 + d]), acc);
    }
    outh[(size_t)m * DINC + d] = __float2half_rn(siluf(acc));
}

// ---------------------------------------------------------------------------
// Barrier-free selective scan (all-fp16 streams) -> fp16 y
// ---------------------------------------------------------------------------
__global__ void __launch_bounds__(256)
scan_kernel(const __half* __restrict__ dt, const __half* __restrict__ xc,
            const float* __restrict__ xdbl, const float* __restrict__ A_log,
            const float* __restrict__ Dw, const __half* __restrict__ xz,
            __half* __restrict__ y)
{
    const int tid  = threadIdx.x;
    const int lane = tid & 31;
    const int wrp  = tid >> 5;
    const int s    = lane & 15;
    const int dsub = lane >> 4;
    const int d    = blockIdx.x * 16 + wrp * 2 + dsub;
    const int b    = blockIdx.y;

    const float a  = -expf(A_log[d * 16 + s]);
    const float Dv = Dw[d];
    float h = 0.f;

    size_t base = (size_t)(b * SEQT);
    float dtv = __half2float(dt[base * DINC + d]);
    float xcv = __half2float(xc[base * DINC + d]);
    float Bv  = xdbl[base * XDBLC + 64 + s];
    float Cv  = xdbl[base * XDBLC + 80 + s];

    for (int t = 0; t < SEQT; t++) {
        const size_t cur = base + t;
        float ndt = 0.f, nxc = 0.f, nB = 0.f, nC = 0.f;
        if (t + 1 < SEQT) {
            const size_t nxt = cur + 1;
            ndt = __half2float(dt[nxt * DINC + d]);
            nxc = __half2float(xc[nxt * DINC + d]);
            nB  = xdbl[nxt * XDBLC + 64 + s];
            nC  = xdbl[nxt * XDBLC + 80 + s];
        }
        h = __expf(dtv * a) * h + dtv * Bv * xcv;
        float p = h * Cv;
        p += __shfl_xor_sync(0xffffffffu, p, 1);
        p += __shfl_xor_sync(0xffffffffu, p, 2);
        p += __shfl_xor_sync(0xffffffffu, p, 4);
        p += __shfl_xor_sync(0xffffffffu, p, 8);
        if (s == 0) {
            const float zv = __half2float(xz[cur * 4096 + 2048 + d]);
            y[cur * DINC + d] =
                __float2half_rn((p + Dv * xcv) * (zv / (1.0f + __expf(-zv))));
        }
        dtv = ndt; xcv = nxc; Bv = nB; Cv = nC;
    }
}

// ---------------------------------------------------------------------------
// Causal attention, fully tensor-core (R14/R15).
// ---------------------------------------------------------------------------
#define QT 16
__global__ void __launch_bounds__(256)
attn_tile_kernel(const __half* __restrict__ qkv, __half* __restrict__ out)
{
    const int qt = blockIdx.x;
    const int h  = blockIdx.y;
    const int b  = blockIdx.z;
    const int i0 = qt * QT;
    const int tid  = threadIdx.x;
    const int lane = tid & 31;
    const int warp = tid >> 5;
    const int g    = lane >> 2;
    const int ac   = lane & 3;
    const int jmax = min(i0 + QT, SEQT);
    const int jtiles = (jmax + 7) >> 3;

    __shared__ __align__(16) __half Qs[16 * 72];
    __shared__ __align__(16) __half Ks[160 * 72];
    __shared__ __align__(16) __half Ps[16 * 168];
    __shared__ float S[QT][152];
    __shared__ float sinv[QT];

    const size_t base_bh = (size_t)(b * SEQT) * 12288 + (size_t)h * 1024;

    float accS[3][4];
#pragma unroll
    for (int t = 0; t < 3; t++)
#pragma unroll
        for (int r = 0; r < 4; r++) accS[t][r] = 0.0f;

    for (int kc = 0; kc < 16; kc++) {
        {
            const int row = tid >> 4;
            const int dg  = tid & 15;
            const int qrow = min(i0 + row, SEQT - 1);
            *reinterpret_cast<uint2*>(&Qs[row * 72 + dg * 4]) =
                *reinterpret_cast<const uint2*>(
                    qkv + base_bh + (size_t)qrow * 12288 + kc * 64 + dg * 4);
        }
#pragma unroll
        for (int it = 0; it < 10; it++) {
            const int idx = tid + it * 256;
            const int row = idx >> 4;
            const int dg  = idx & 15;
            uint2 o = make_uint2(0u, 0u);
            if (row < jmax)
                o = *reinterpret_cast<const uint2*>(
                    qkv + base_bh + (size_t)row * 12288 + 4096 + kc * 64 + dg * 4);
            *reinterpret_cast<uint2*>(&Ks[row * 72 + dg * 4]) = o;
        }
        __syncthreads();

#pragma unroll
        for (int ks = 0; ks < 4; ks++) {
            const int kk = ks * 16;
            uint32_t af0 = ldh2(&Qs[(g    ) * 72 + kk + ac * 2    ]);
            uint32_t af1 = ldh2(&Qs[(g + 8) * 72 + kk + ac * 2    ]);
            uint32_t af2 = ldh2(&Qs[(g    ) * 72 + kk + ac * 2 + 8]);
            uint32_t af3 = ldh2(&Qs[(g + 8) * 72 + kk + ac * 2 + 8]);
#pragma unroll
            for (int tt = 0; tt < 3; tt++) {
                const int nt = warp + tt * 8;
                if (nt < jtiles) {
                    const int c = nt * 8 + g;
                    uint32_t bf0 = ldh2(&Ks[c * 72 + kk + ac * 2    ]);
                    uint32_t bf1 = ldh2(&Ks[c * 72 + kk + ac * 2 + 8]);
                    mma_f16(accS[tt], af0, af1, af2, af3, bf0, bf1);
                }
            }
        }
        __syncthreads();
    }

#pragma unroll
    for (int tt = 0; tt < 3; tt++) {
        const int nt = warp + tt * 8;
        if (nt < jtiles) {
            const int j0 = nt * 8 + ac * 2;
            const int r0 = i0 + g;
            const int r1 = i0 + g + 8;
            S[g][j0]         = (j0     <= r0) ? accS[tt][0] * 0.03125f : -1e30f;
            S[g][j0 + 1]     = (j0 + 1 <= r0) ? accS[tt][1] * 0.03125f : -1e30f;
            S[g + 8][j0]     = (j0     <= r1) ? accS[tt][2] * 0.03125f : -1e30f;
            S[g + 8][j0 + 1] = (j0 + 1 <= r1) ? accS[tt][3] * 0.03125f : -1e30f;
        }
    }
    __syncthreads();

    {
        for (int qq = warp; qq < QT; qq += 8) {
            float m = -3.0e38f;
            for (int j = lane; j < jmax; j += 32) m = fmaxf(m, S[qq][j]);
#pragma unroll
            for (int o = 16; o; o >>= 1) m = fmaxf(m, __shfl_xor_sync(0xffffffffu, m, o));
            float sm = 0.f;
            for (int j = lane; j < jmax; j += 32) {
                const float e = __expf(S[qq][j] - m);
                S[qq][j] = e;
                sm += e;
            }
#pragma unroll
            for (int o = 16; o; o >>= 1) sm += __shfl_xor_sync(0xffffffffu, sm, o);
            if (lane == 0) sinv[qq] = 1.0f / sm;
        }
    }
    __syncthreads();

    for (int qq = warp; qq < QT; qq += 8) {
        const float inv = sinv[qq];
        for (int j = lane; j < 160; j += 32)
            Ps[qq * 168 + j] = __float2half_rn(j < jmax ? S[qq][j] * inv : 0.f);
    }
    __syncthreads();

    const int nb_w = warp * 8;
    for (int dc = 0; dc < 16; dc++) {
#pragma unroll
        for (int it = 0; it < 10; it++) {
            const int idx = tid + it * 256;
            const int row = idx >> 4;
            const int dg  = idx & 15;
            uint2 o = make_uint2(0u, 0u);
            if (row < jmax)
                o = *reinterpret_cast<const uint2*>(
                    qkv + base_bh + (size_t)row * 12288 + 8192 + dc * 64 + dg * 4);
            *reinterpret_cast<uint2*>(&Ks[row * 72 + dg * 4]) = o;
        }
        __syncthreads();

        float c[4] = {0.f, 0.f, 0.f, 0.f};
#pragma unroll
        for (int kt = 0; kt < 10; kt++) {
            const int kk = kt * 16;
            uint32_t a0 = ldh2(&Ps[(g    ) * 168 + kk + ac * 2    ]);
            uint32_t a1 = ldh2(&Ps[(g + 8) * 168 + kk + ac * 2    ]);
            uint32_t a2 = ldh2(&Ps[(g    ) * 168 + kk + ac * 2 + 8]);
            uint32_t a3 = ldh2(&Ps[(g + 8) * 168 + kk + ac * 2 + 8]);
            uint32_t b0, b1;
            ldsm_x2_trans(b0, b1,
                          smem_u32(&Ks[(kk + (lane & 15)) * 72 + nb_w]));
            mma_f16(c, a0, a1, a2, a3, b0, b1);
        }

        const int r0 = i0 + g;
        const int r1 = i0 + g + 8;
        const int dcol = dc * 64 + nb_w + ac * 2;
        if (r0 < SEQT) {
            __half2 hh = __floats2half2_rn(c[0], c[1]);
            *reinterpret_cast<uint32_t*>(
                out + (size_t)(b * SEQT + r0) * INNERC + (size_t)h * 1024 + dcol) =
                *reinterpret_cast<uint32_t*>(&hh);
        }
        if (r1 < SEQT) {
            __half2 hh = __floats2half2_rn(c[2], c[3]);
            *reinterpret_cast<uint32_t*>(
                out + (size_t)(b * SEQT + r1) * INNERC + (size_t)h * 1024 + dcol) =
                *reinterpret_cast<uint32_t*>(&hh);
        }
        __syncthreads();
    }
}

// ---------------------------------------------------------------------------
extern "C" void kernel_launch(void* const* d_in, const int* in_sizes, int n_in,
                              void* d_out, int out_size)
{
    const float* features    = (const float*)d_in[0];
    const float* mnorm_w     = (const float*)d_in[1];
    const float* mnorm_b     = (const float*)d_in[2];
    const float* in_proj_w   = (const float*)d_in[3];
    const float* conv_w      = (const float*)d_in[4];
    const float* conv_b      = (const float*)d_in[5];
    const float* x_proj_w    = (const float*)d_in[6];
    const float* dt_proj_w   = (const float*)d_in[7];
    const float* dt_proj_b   = (const float*)d_in[8];
    const float* A_log       = (const float*)d_in[9];
    const float* D_skip      = (const float*)d_in[10];
    const float* mamba_out_w = (const float*)d_in[11];
    const float* ln1_w       = (const float*)d_in[12];
    const float* ln1_b       = (const float*)d_in[13];
    const float* qkv_w       = (const float*)d_in[14];
    const float* attn_out_w  = (const float*)d_in[15];
    const float* attn_out_b  = (const float*)d_in[16];
    const float* ln2_w       = (const float*)d_in[17];
    const float* ln2_b       = (const float*)d_in[18];
    const float* ffn_w1      = (const float*)d_in[19];
    const float* ffn_b1      = (const float*)d_in[20];
    const float* ffn_w2      = (const float*)d_in[21];
    const float* ffn_b2      = (const float*)d_in[22];

    float  *p_xdbl, *p_xpart;
    __half *p_normh, *p_xzh, *p_xch, *p_xdbl16, *p_dth, *p_yh, *p_qkvh, *p_attnh, *p_ffnh, *p_part2;
    __half *w_inproj, *w_xproj, *w_dt, *w_mamba, *w_qkv, *w_attn, *w_ffn1, *w_ffn2;
    cudaGetSymbolAddress((void**)&p_normh,  g_normh);
    cudaGetSymbolAddress((void**)&p_xzh,    g_xzh);
    cudaGetSymbolAddress((void**)&p_xch,    g_xch);
    cudaGetSymbolAddress((void**)&p_xdbl,   g_xdbl);
    cudaGetSymbolAddress((void**)&p_xdbl16, g_xdbl16);
    cudaGetSymbolAddress((void**)&p_xpart,  g_xpart);
    cudaGetSymbolAddress((void**)&p_dth,    g_dth);
    cudaGetSymbolAddress((void**)&p_yh,     g_yh);
    cudaGetSymbolAddress((void**)&p_qkvh,   g_qkvh);
    cudaGetSymbolAddress((void**)&p_attnh,  g_attnh);
    cudaGetSymbolAddress((void**)&p_ffnh,   g_ffnh);
    cudaGetSymbolAddress((void**)&p_part2,  g_part2);
    cudaGetSymbolAddress((void**)&w_inproj, g_w_inproj);
    cudaGetSymbolAddress((void**)&w_xproj,  g_w_xproj);
    cudaGetSymbolAddress((void**)&w_dt,     g_w_dt);
    cudaGetSymbolAddress((void**)&w_mamba,  g_w_mamba);
    cudaGetSymbolAddress((void**)&w_qkv,    g_w_qkv);
    cudaGetSymbolAddress((void**)&w_attn,   g_w_attn);
    cudaGetSymbolAddress((void**)&w_ffn1,   g_w_ffn1);
    cudaGetSymbolAddress((void**)&w_ffn2,   g_w_ffn2);

    const int SMH  = 4 * (64 + 128) * 40 * 2;   // 61440 (BN=128)
    const int SMH2 = 4 * (64 + 256) * 40 * 2;   // 102400 (BN=256)
    cudaFuncSetAttribute((gemm_h<1, 1, 256>), cudaFuncAttributeMaxDynamicSharedMemorySize, SMH2);
    cudaFuncSetAttribute((gemm_h<2, 1, 256>), cudaFuncAttributeMaxDynamicSharedMemorySize, SMH2);
    cudaFuncSetAttribute((gemm_h<0, SKR, 256>), cudaFuncAttributeMaxDynamicSharedMemorySize, SMH2);
    cudaFuncSetAttribute((gemm_h<6, 1, 128>), cudaFuncAttributeMaxDynamicSharedMemorySize, SMH);
    cudaFuncSetAttribute((gemm_h<0, XKS, 128>), cudaFuncAttributeMaxDynamicSharedMemorySize, SMH);

    // ---- weight conversion ----
    auto conv16 = [&](const float* src, __half* dst, size_t n) {
        const int n4 = (int)(n / 4);
        f32to16<<<(n4 + 255) / 256, 256>>>(src, dst, n4);
    };
    conv16(in_proj_w,   w_inproj, (size_t)DEPTHC * 4096 * DIMC);
    conv16(x_proj_w,    w_xproj,  (size_t)DEPTHC * XDBLC * DINC);
    conv16(dt_proj_w,   w_dt,     (size_t)DEPTHC * DINC * DTRANK);
    conv16(mamba_out_w, w_mamba,  (size_t)DEPTHC * DIMC * DINC);
    conv16(qkv_w,       w_qkv,    (size_t)DEPTHC * 3 * INNERC * DIMC);
    conv16(attn_out_w,  w_attn,   (size_t)DEPTHC * DIMC * INNERC);
    conv16(ffn_w1,      w_ffn1,   (size_t)DEPTHC * MLPC * DIMC);
    conv16(ffn_w2,      w_ffn2,   (size_t)DEPTHC * DIMC * MLPC);

    float* X = (float*)d_out;
    cudaMemcpyAsync(X, features, sizeof(float) * (size_t)MTOT * DIMC,
                    cudaMemcpyDeviceToDevice);

    ln_kernel<<<MTOT, 256>>>(X, mnorm_w, mnorm_b, p_normh);

    // xproj fp16 partial buffer aliases the big part2 buffer region? No:
    // keep the dedicated fp32 xpart? We reuse fp16 partials via part2? They
    // overlap in time with nothing else between xproj gemm and reduce; but
    // part2 has capacity SKR*MTOT*DIMC halves = 4*1200*1024 >= 8*1200*96.
    __half* p_xpart16 = p_part2;

    for (int i = 0; i < DEPTHC; i++) {
        // ---- Mamba ----
        gemm_h<1, 1, 256><<<dim3(16, 19), 256, SMH2>>>(p_normh, DIMC,
                w_inproj + (size_t)i * 4096 * DIMC, DIMC,
                nullptr, p_xzh, 4096, MTOT, 4096, DIMC);
        conv_kernel<<<dim3(MTOT, 8), 256>>>(p_xzh, conv_w + (size_t)i * DINC * 4,
                                            conv_b + i * DINC, p_xch);
        gemm_h<0, XKS, 128><<<dim3(1, 19, XKS), 256, SMH>>>(p_xch, DINC,
                w_xproj + (size_t)i * XDBLC * DINC, DINC,
                nullptr, p_xpart16, XDBLC, MTOT, XDBLC, DINC);
        xproj_reduce_h<<<(MTOT * XDBLC + 255) / 256, 256>>>(p_xpart16, p_xdbl, p_xdbl16);
        gemm_h<6, 1, 128><<<dim3(16, 19), 256, SMH>>>(p_xdbl16, XDBLC,
                w_dt + (size_t)i * DINC * DTRANK, DTRANK,
                dt_proj_b + i * DINC, p_dth, DINC, MTOT, DINC, DTRANK);
        scan_kernel<<<dim3(128, BATCH), 256>>>(p_dth, p_xch, p_xdbl,
                A_log + (size_t)i * DINC * DSTATE,
                D_skip + i * DINC, p_xzh, p_yh);
        gemm_h<0, SKR, 256><<<dim3(4, 19, SKR), 256, SMH2>>>(p_yh, DINC,
                w_mamba + (size_t)i * DIMC * DINC, DINC,
                nullptr, p_part2, DIMC, MTOT, DIMC, DINC);
        reduce_ln<3, true><<<MTOT, 256>>>(p_part2, nullptr, X,
                ln1_w + i * DIMC, ln1_b + i * DIMC, p_normh);

        // ---- Attention ----
        gemm_h<1, 1, 256><<<dim3(48, 19), 256, SMH2>>>(p_normh, DIMC,
                w_qkv + (size_t)i * 3 * INNERC * DIMC, DIMC,
                nullptr, p_qkvh, 3 * INNERC, MTOT, 3 * INNERC, DIMC);
        attn_tile_kernel<<<dim3(10, 4, BATCH), 256>>>(p_qkvh, p_attnh);
        gemm_h<0, SKR, 256><<<dim3(4, 19, SKR), 256, SMH2>>>(p_attnh, INNERC,
                w_attn + (size_t)i * DIMC * INNERC, INNERC,
                nullptr, p_part2, DIMC, MTOT, DIMC, INNERC);
        reduce_ln<4, true><<<MTOT, 256>>>(p_part2, attn_out_b + i * DIMC, X,
                ln2_w + i * DIMC, ln2_b + i * DIMC, p_normh);

        // ---- FFN ----
        gemm_h<2, 1, 256><<<dim3(16, 19), 256, SMH2>>>(p_normh, DIMC,
                w_ffn1 + (size_t)i * MLPC * DIMC, DIMC,
                ffn_b1 + i * MLPC, p_ffnh, MLPC, MTOT, MLPC, DIMC);
        gemm_h<0, SKR, 256><<<dim3(4, 19, SKR), 256, SMH2>>>(p_ffnh, MLPC,
                w_ffn2 + (size_t)i * DIMC * MLPC, MLPC,
                nullptr, p_part2, DIMC, MTOT, DIMC, MLPC);
        if (i + 1 < DEPTHC)
            reduce_ln<3, true><<<MTOT, 256>>>(p_part2, ffn_b2 + i * DIMC, X,
                    mnorm_w + (i + 1) * DIMC, mnorm_b + (i + 1) * DIMC, p_normh);
        else
            reduce_ln<3, false><<<MTOT, 256>>>(p_part2, ffn_b2 + i * DIMC, X,
                    nullptr, nullptr, nullptr);
    }
}

// round 17
// speedup vs baseline: 1.1219x; 1.1219x over previous
#include <cuda_runtime.h>
#include <cuda_fp16.h>
#include <math.h>
#include <stdint.h>

// ---------------------------------------------------------------------------
#define BATCH   8
#define SEQT    150
#define MTOT    1200
#define DIMC    1024
#define DINC    2048
#define DSTATE  16
#define DTRANK  64
#define XDBLC   96
#define INNERC  4096
#define MLPC    4096
#define DEPTHC  5
#define XKS     8
#define SKR     4

// ---------------------------------------------------------------------------
// Scratch (R15 layout: fp32 partials, fp32 xc for scan + fp16 twin)
// ---------------------------------------------------------------------------
__device__ __half g_normh [MTOT * DIMC];
__device__ __half g_xzh   [MTOT * 2 * DINC];
__device__ float  g_xc    [MTOT * DINC];
__device__ __half g_xch   [MTOT * DINC];
__device__ float  g_xdbl  [MTOT * XDBLC];
__device__ __half g_xdbl16[MTOT * XDBLC];
__device__ float  g_xpart [XKS * MTOT * XDBLC];
__device__ __half g_dth   [MTOT * DINC];
__device__ __half g_yh    [MTOT * DINC];
__device__ __half g_qkvh  [MTOT * 3 * INNERC];
__device__ __half g_attnh [MTOT * INNERC];
__device__ __half g_ffnh  [MTOT * MLPC];
__device__ float  g_part2 [SKR * MTOT * DIMC];

// fp16 weight copies (converted each launch; deterministic)
__device__ __half g_w_inproj[DEPTHC * 4096 * DIMC];
__device__ __half g_w_xproj [DEPTHC * XDBLC * DINC];
__device__ __half g_w_dt    [DEPTHC * DINC * DTRANK];
__device__ __half g_w_mamba [DEPTHC * DIMC * DINC];
__device__ __half g_w_qkv   [DEPTHC * 3 * INNERC * DIMC];
__device__ __half g_w_attn  [DEPTHC * DIMC * INNERC];
__device__ __half g_w_ffn1  [DEPTHC * MLPC * DIMC];
__device__ __half g_w_ffn2  [DEPTHC * DIMC * MLPC];

// ---------------------------------------------------------------------------
__device__ __forceinline__ float geluf(float x) {
    return 0.5f * x * (1.0f + erff(x * 0.70710678118654752f));
}
__device__ __forceinline__ float softplusf(float x) {
    return fmaxf(x, 0.0f) + log1pf(__expf(-fabsf(x)));
}
__device__ __forceinline__ float siluf(float x) {
    return x / (1.0f + __expf(-x));
}
__device__ __forceinline__ uint32_t ldh2(const __half* p) {
    return *reinterpret_cast<const uint32_t*>(p);
}
__device__ __forceinline__ void mma_f16(float c[4],
                                        uint32_t a0, uint32_t a1, uint32_t a2, uint32_t a3,
                                        uint32_t b0, uint32_t b1) {
    asm volatile(
        "mma.sync.aligned.m16n8k16.row.col.f32.f16.f16.f32 "
        "{%0,%1,%2,%3}, {%4,%5,%6,%7}, {%8,%9}, {%0,%1,%2,%3};"
        : "+f"(c[0]), "+f"(c[1]), "+f"(c[2]), "+f"(c[3])
        : "r"(a0), "r"(a1), "r"(a2), "r"(a3), "r"(b0), "r"(b1));
}
__device__ __forceinline__ void ldsm_x2_trans(uint32_t& b0, uint32_t& b1,
                                              uint32_t saddr) {
    asm volatile("ldmatrix.sync.aligned.m8n8.x2.trans.shared.b16 {%0,%1}, [%2];"
                 : "=r"(b0), "=r"(b1) : "r"(saddr));
}
__device__ __forceinline__ void cp16(uint32_t dst, const void* src, int sz) {
    asm volatile("cp.async.cg.shared.global [%0], [%1], 16, %2;"
                 :: "r"(dst), "l"(src), "r"(sz));
}
__device__ __forceinline__ uint32_t smem_u32(const void* p) {
    return (uint32_t)__cvta_generic_to_shared(p);
}

// ---------------------------------------------------------------------------
// fp32 -> fp16 bulk convert
// ---------------------------------------------------------------------------
__global__ void __launch_bounds__(256)
f32to16(const float* __restrict__ in, __half* __restrict__ out, int n4)
{
    const int i = blockIdx.x * 256 + threadIdx.x;
    if (i >= n4) return;
    const float4 v = reinterpret_cast<const float4*>(in)[i];
    __half2 h0 = __floats2half2_rn(v.x, v.y);
    __half2 h1 = __floats2half2_rn(v.z, v.w);
    uint2 o;
    o.x = *reinterpret_cast<uint32_t*>(&h0);
    o.y = *reinterpret_cast<uint32_t*>(&h1);
    reinterpret_cast<uint2*>(out)[i] = o;
}

// ---------------------------------------------------------------------------
// fp16 mma.sync GEMM with vectorized epilogue stores (half2 / float2).
// SK>1: blockIdx.z K-slice -> fp32 partials at C[z*M*N + m*ldc + n].
// EPI (SK==1): 1=fp16  2=gelu(+bias)->fp16  6=softplus(+bias)->fp16
// ---------------------------------------------------------------------------
template <int EPI, int SK, int BN>
__global__ void __launch_bounds__(256, 2)
gemm_h(const __half* __restrict__ A, int lda,
       const __half* __restrict__ B, int ldb,
       const float* __restrict__ bias,
       void* __restrict__ Cv, int ldc,
       int M, int N, int K)
{
    constexpr int PAD = 40;
    constexpr int NJ  = BN / 32;
    constexpr int BRQ = BN / 64;
    extern __shared__ __half smh[];
    __half* sA = smh;
    __half* sB = smh + 4 * 64 * PAD;

    const int m0    = blockIdx.y * 64;
    const int n0    = blockIdx.x * BN;
    const int Ks    = K / SK;
    const int kbase = (SK > 1) ? blockIdx.z * Ks : 0;
    const int tid   = threadIdx.x;
    const int lane  = tid & 31;
    const int warp  = tid >> 5;
    const int wm    = warp & 1;
    const int wn    = warp >> 1;
    const int g     = lane >> 2;
    const int ac    = lane & 3;
    const int NIT   = Ks >> 5;

    float acc[2][NJ][4];
#pragma unroll
    for (int i = 0; i < 2; i++)
#pragma unroll
        for (int j = 0; j < NJ; j++)
#pragma unroll
            for (int r = 0; r < 4; r++) acc[i][j][r] = 0.0f;

    auto issue = [&](int s, int k0, bool real) {
        if (real) {
            {
                const int row = tid >> 2;
                const int kq  = (tid & 3) * 8;
                cp16(smem_u32(&sA[(s * 64 + row) * PAD + kq]),
                     &A[(size_t)(m0 + row) * lda + kbase + k0 + kq],
                     (m0 + row < M) ? 16 : 0);
            }
#pragma unroll
            for (int r = 0; r < BRQ; r++) {
                const int idx = tid + r * 256;
                const int row = idx >> 2;
                const int kq  = (idx & 3) * 8;
                cp16(smem_u32(&sB[(s * BN + row) * PAD + kq]),
                     &B[(size_t)(n0 + row) * ldb + kbase + k0 + kq],
                     (n0 + row < N) ? 16 : 0);
            }
        }
        asm volatile("cp.async.commit_group;");
    };

    issue(0, 0, true);
    issue(1, 32, 1 < NIT);
    issue(2, 64, 2 < NIT);

    for (int it = 0; it < NIT; it++) {
        const int p = it & 3;
        asm volatile("cp.async.wait_group 2;");
        __syncthreads();
        issue((it + 3) & 3, (it + 3) << 5, (it + 3) < NIT);

        const __half* pa = &sA[p * 64 * PAD];
        const __half* pb = &sB[p * BN * PAD];
#pragma unroll
        for (int ks = 0; ks < 2; ks++) {
            const int kk = ks * 16;
            uint32_t af[2][4], bf[NJ][2];
#pragma unroll
            for (int i = 0; i < 2; i++) {
                const int r = wm * 32 + i * 16 + g;
                af[i][0] = ldh2(&pa[(r    ) * PAD + kk + ac * 2    ]);
                af[i][1] = ldh2(&pa[(r + 8) * PAD + kk + ac * 2    ]);
                af[i][2] = ldh2(&pa[(r    ) * PAD + kk + ac * 2 + 8]);
                af[i][3] = ldh2(&pa[(r + 8) * PAD + kk + ac * 2 + 8]);
            }
#pragma unroll
            for (int j = 0; j < NJ; j++) {
                const int c = wn * (8 * NJ) + j * 8 + g;
                bf[j][0] = ldh2(&pb[c * PAD + kk + ac * 2    ]);
                bf[j][1] = ldh2(&pb[c * PAD + kk + ac * 2 + 8]);
            }
#pragma unroll
            for (int i = 0; i < 2; i++)
#pragma unroll
                for (int j = 0; j < NJ; j++)
                    mma_f16(acc[i][j], af[i][0], af[i][1], af[i][2], af[i][3],
                            bf[j][0], bf[j][1]);
        }
        __syncthreads();
    }

    // Vectorized epilogue: each accumulator pair (n, n+1) is contiguous.
    const size_t zoff = (SK > 1) ? (size_t)blockIdx.z * M * N : 0;
#pragma unroll
    for (int i = 0; i < 2; i++) {
#pragma unroll
        for (int j = 0; j < NJ; j++) {
            const int mb = m0 + wm * 32 + i * 16 + g;
            const int n  = n0 + wn * (8 * NJ) + j * 8 + ac * 2;  // even
            if (n >= N) continue;          // N even => n+1 < N too
#pragma unroll
            for (int r2 = 0; r2 < 2; r2++) {
                const int m = mb + r2 * 8;
                if (m >= M) continue;
                const size_t o = zoff + (size_t)m * ldc + n;
                float v0 = acc[i][j][r2 * 2 + 0];
                float v1 = acc[i][j][r2 * 2 + 1];
                if (SK > 1) {
                    *reinterpret_cast<float2*>((float*)Cv + o) =
                        make_float2(v0, v1);
                } else {
                    if (EPI == 2) { v0 = geluf(v0 + bias[n]); v1 = geluf(v1 + bias[n + 1]); }
                    else if (EPI == 6) { v0 = softplusf(v0 + bias[n]); v1 = softplusf(v1 + bias[n + 1]); }
                    __half2 hh = __floats2half2_rn(v0, v1);
                    *reinterpret_cast<uint32_t*>((__half*)Cv + o) =
                        *reinterpret_cast<uint32_t*>(&hh);
                }
            }
        }
    }
}

// ---------------------------------------------------------------------------
// Fused split-K reduce (SKR fp32 partials) + residual epilogue + LayerNorm.
// ---------------------------------------------------------------------------
template <int EPI, bool DOLN>
__global__ void __launch_bounds__(256)
reduce_ln(const float* __restrict__ part, const float* __restrict__ bias,
          float* __restrict__ X,
          const float* __restrict__ lnw, const float* __restrict__ lnb,
          __half* __restrict__ normh)
{
    const int row = blockIdx.x;
    const int tid = threadIdx.x;
    __shared__ float red[8];

    float v[4];
    float s = 0.f;
#pragma unroll
    for (int u = 0; u < 4; u++) {
        const int c = tid + u * 256;
        const size_t idx = (size_t)row * DIMC + c;
        float f = 0.f;
#pragma unroll
        for (int z = 0; z < SKR; z++)
            f += part[idx + (size_t)z * MTOT * DIMC];
        float nx;
        if (EPI == 3) nx = X[idx] + f + (bias ? bias[c] : 0.0f);
        else          nx = X[idx] + geluf(f + bias[c]);
        X[idx] = nx;
        v[u] = nx;
        s += nx;
    }
    if (!DOLN) return;

#pragma unroll
    for (int o = 16; o; o >>= 1) s += __shfl_xor_sync(0xffffffffu, s, o);
    if ((tid & 31) == 0) red[tid >> 5] = s;
    __syncthreads();
    float tot = 0.f;
#pragma unroll
    for (int u = 0; u < 8; u++) tot += red[u];
    const float mu = tot * (1.0f / 1024.0f);

    float s2 = 0.f;
#pragma unroll
    for (int u = 0; u < 4; u++) { const float d = v[u] - mu; s2 += d * d; }
    __syncthreads();
#pragma unroll
    for (int o = 16; o; o >>= 1) s2 += __shfl_xor_sync(0xffffffffu, s2, o);
    if ((tid & 31) == 0) red[tid >> 5] = s2;
    __syncthreads();
    float tot2 = 0.f;
#pragma unroll
    for (int u = 0; u < 8; u++) tot2 += red[u];
    const float rstd = rsqrtf(tot2 * (1.0f / 1024.0f) + 1e-5f);

    __half* orow = normh + (size_t)row * DIMC;
#pragma unroll
    for (int u = 0; u < 4; u++) {
        const int c = tid + u * 256;
        orow[c] = __float2half_rn((v[u] - mu) * rstd * lnw[c] + lnb[c]);
    }
}

// ---------------------------------------------------------------------------
__global__ void __launch_bounds__(256)
xproj_reduce(const float* __restrict__ part, float* __restrict__ C,
             __half* __restrict__ Ch)
{
    const int idx = blockIdx.x * 256 + threadIdx.x;
    if (idx >= MTOT * XDBLC) return;
    float s = 0.f;
#pragma unroll
    for (int ks = 0; ks < XKS; ks++)
        s += part[(size_t)ks * MTOT * XDBLC + idx];
    C[idx]  = s;
    Ch[idx] = __float2half_rn(s);
}

// ---------------------------------------------------------------------------
__global__ void __launch_bounds__(256)
ln_kernel(const float* __restrict__ x, const float* __restrict__ w,
          const float* __restrict__ b, __half* __restrict__ out)
{
    const int row = blockIdx.x;
    const int tid = threadIdx.x;
    const float* xr = x + (size_t)row * DIMC;
    __shared__ float red[8];

    float v[4];
    float s = 0.f;
#pragma unroll
    for (int u = 0; u < 4; u++) { v[u] = xr[tid + u * 256]; s += v[u]; }
#pragma unroll
    for (int o = 16; o; o >>= 1) s += __shfl_xor_sync(0xffffffffu, s, o);
    if ((tid & 31) == 0) red[tid >> 5] = s;
    __syncthreads();
    float tot = 0.f;
#pragma unroll
    for (int u = 0; u < 8; u++) tot += red[u];
    const float mu = tot * (1.0f / 1024.0f);

    float s2 = 0.f;
#pragma unroll
    for (int u = 0; u < 4; u++) { const float d = v[u] - mu; s2 += d * d; }
    __syncthreads();
#pragma unroll
    for (int o = 16; o; o >>= 1) s2 += __shfl_xor_sync(0xffffffffu, s2, o);
    if ((tid & 31) == 0) red[tid >> 5] = s2;
    __syncthreads();
    float tot2 = 0.f;
#pragma unroll
    for (int u = 0; u < 8; u++) tot2 += red[u];
    const float rstd = rsqrtf(tot2 * (1.0f / 1024.0f) + 1e-5f);

    __half* orow = out + (size_t)row * DIMC;
#pragma unroll
    for (int u = 0; u < 4; u++) {
        const int c = tid + u * 256;
        orow[c] = __float2half_rn((v[u] - mu) * rstd * w[c] + b[c]);
    }
}

// ---------------------------------------------------------------------------
// Depthwise causal conv on fp16 xz -> fp32 xc (scan) + fp16 xch (x_proj)
// ---------------------------------------------------------------------------
__global__ void __launch_bounds__(256)
conv_kernel(const __half* __restrict__ xz, const float* __restrict__ cw,
            const float* __restrict__ cb, float* __restrict__ out,
            __half* __restrict__ outh)
{
    const int m = blockIdx.x;
    const int d = blockIdx.y * 256 + threadIdx.x;
    const int b = m / SEQT, t = m % SEQT;
    float acc = cb[d];
#pragma unroll
    for (int j = 0; j < 4; j++) {
        const int tt = t + j - 3;
        if (tt >= 0)
            acc = fmaf(cw[d * 4 + j],
                       __half2float(xz[((size_t)(b * SEQT + tt)) * 4096 + d]), acc);
    }
    const float r = siluf(acc);
    out [(size_t)m * DINC + d] = r;
    outh[(size_t)m * DINC + d] = __float2half_rn(r);
}

// ---------------------------------------------------------------------------
// Barrier-free selective scan (fp16 dt/z, fp32 xc) -> fp16 y
// ---------------------------------------------------------------------------
__global__ void __launch_bounds__(256)
scan_kernel(const __half* __restrict__ dt, const float* __restrict__ xc,
            const float* __restrict__ xdbl, const float* __restrict__ A_log,
            const float* __restrict__ Dw, const __half* __restrict__ xz,
            __half* __restrict__ y)
{
    const int tid  = threadIdx.x;
    const int lane = tid & 31;
    const int wrp  = tid >> 5;
    const int s    = lane & 15;
    const int dsub = lane >> 4;
    const int d    = blockIdx.x * 16 + wrp * 2 + dsub;
    const int b    = blockIdx.y;

    const float a  = -expf(A_log[d * 16 + s]);
    const float Dv = Dw[d];
    float h = 0.f;

    size_t base = (size_t)(b * SEQT);
    float dtv = __half2float(dt[base * DINC + d]);
    float xcv = xc[base * DINC + d];
    float Bv  = xdbl[base * XDBLC + 64 + s];
    float Cv  = xdbl[base * XDBLC + 80 + s];

    for (int t = 0; t < SEQT; t++) {
        const size_t cur = base + t;
        float ndt = 0.f, nxc = 0.f, nB = 0.f, nC = 0.f;
        if (t + 1 < SEQT) {
            const size_t nxt = cur + 1;
            ndt = __half2float(dt[nxt * DINC + d]);
            nxc = xc[nxt * DINC + d];
            nB  = xdbl[nxt * XDBLC + 64 + s];
            nC  = xdbl[nxt * XDBLC + 80 + s];
        }
        h = __expf(dtv * a) * h + dtv * Bv * xcv;
        float p = h * Cv;
        p += __shfl_xor_sync(0xffffffffu, p, 1);
        p += __shfl_xor_sync(0xffffffffu, p, 2);
        p += __shfl_xor_sync(0xffffffffu, p, 4);
        p += __shfl_xor_sync(0xffffffffu, p, 8);
        if (s == 0) {
            const float zv = __half2float(xz[cur * 4096 + 2048 + d]);
            y[cur * DINC + d] =
                __float2half_rn((p + Dv * xcv) * (zv / (1.0f + __expf(-zv))));
        }
        dtv = ndt; xcv = nxc; Bv = nB; Cv = nC;
    }
}

// ---------------------------------------------------------------------------
// Causal attention, fully tensor-core (R14/R15).
// ---------------------------------------------------------------------------
#define QT 16
__global__ void __launch_bounds__(256)
attn_tile_kernel(const __half* __restrict__ qkv, __half* __restrict__ out)
{
    const int qt = blockIdx.x;
    const int h  = blockIdx.y;
    const int b  = blockIdx.z;
    const int i0 = qt * QT;
    const int tid  = threadIdx.x;
    const int lane = tid & 31;
    const int warp = tid >> 5;
    const int g    = lane >> 2;
    const int ac   = lane & 3;
    const int jmax = min(i0 + QT, SEQT);
    const int jtiles = (jmax + 7) >> 3;

    __shared__ __align__(16) __half Qs[16 * 72];
    __shared__ __align__(16) __half Ks[160 * 72];
    __shared__ __align__(16) __half Ps[16 * 168];
    __shared__ float S[QT][152];
    __shared__ float sinv[QT];

    const size_t base_bh = (size_t)(b * SEQT) * 12288 + (size_t)h * 1024;

    float accS[3][4];
#pragma unroll
    for (int t = 0; t < 3; t++)
#pragma unroll
        for (int r = 0; r < 4; r++) accS[t][r] = 0.0f;

    for (int kc = 0; kc < 16; kc++) {
        {
            const int row = tid >> 4;
            const int dg  = tid & 15;
            const int qrow = min(i0 + row, SEQT - 1);
            *reinterpret_cast<uint2*>(&Qs[row * 72 + dg * 4]) =
                *reinterpret_cast<const uint2*>(
                    qkv + base_bh + (size_t)qrow * 12288 + kc * 64 + dg * 4);
        }
#pragma unroll
        for (int it = 0; it < 10; it++) {
            const int idx = tid + it * 256;
            const int row = idx >> 4;
            const int dg  = idx & 15;
            uint2 o = make_uint2(0u, 0u);
            if (row < jmax)
                o = *reinterpret_cast<const uint2*>(
                    qkv + base_bh + (size_t)row * 12288 + 4096 + kc * 64 + dg * 4);
            *reinterpret_cast<uint2*>(&Ks[row * 72 + dg * 4]) = o;
        }
        __syncthreads();

#pragma unroll
        for (int ks = 0; ks < 4; ks++) {
            const int kk = ks * 16;
            uint32_t af0 = ldh2(&Qs[(g    ) * 72 + kk + ac * 2    ]);
            uint32_t af1 = ldh2(&Qs[(g + 8) * 72 + kk + ac * 2    ]);
            uint32_t af2 = ldh2(&Qs[(g    ) * 72 + kk + ac * 2 + 8]);
            uint32_t af3 = ldh2(&Qs[(g + 8) * 72 + kk + ac * 2 + 8]);
#pragma unroll
            for (int tt = 0; tt < 3; tt++) {
                const int nt = warp + tt * 8;
                if (nt < jtiles) {
                    const int c = nt * 8 + g;
                    uint32_t bf0 = ldh2(&Ks[c * 72 + kk + ac * 2    ]);
                    uint32_t bf1 = ldh2(&Ks[c * 72 + kk + ac * 2 + 8]);
                    mma_f16(accS[tt], af0, af1, af2, af3, bf0, bf1);
                }
            }
        }
        __syncthreads();
    }

#pragma unroll
    for (int tt = 0; tt < 3; tt++) {
        const int nt = warp + tt * 8;
        if (nt < jtiles) {
            const int j0 = nt * 8 + ac * 2;
            const int r0 = i0 + g;
            const int r1 = i0 + g + 8;
            S[g][j0]         = (j0     <= r0) ? accS[tt][0] * 0.03125f : -1e30f;
            S[g][j0 + 1]     = (j0 + 1 <= r0) ? accS[tt][1] * 0.03125f : -1e30f;
            S[g + 8][j0]     = (j0     <= r1) ? accS[tt][2] * 0.03125f : -1e30f;
            S[g + 8][j0 + 1] = (j0 + 1 <= r1) ? accS[tt][3] * 0.03125f : -1e30f;
        }
    }
    __syncthreads();

    {
        for (int qq = warp; qq < QT; qq += 8) {
            float m = -3.0e38f;
            for (int j = lane; j < jmax; j += 32) m = fmaxf(m, S[qq][j]);
#pragma unroll
            for (int o = 16; o; o >>= 1) m = fmaxf(m, __shfl_xor_sync(0xffffffffu, m, o));
            float sm = 0.f;
            for (int j = lane; j < jmax; j += 32) {
                const float e = __expf(S[qq][j] - m);
                S[qq][j] = e;
                sm += e;
            }
#pragma unroll
            for (int o = 16; o; o >>= 1) sm += __shfl_xor_sync(0xffffffffu, sm, o);
            if (lane == 0) sinv[qq] = 1.0f / sm;
        }
    }
    __syncthreads();

    for (int qq = warp; qq < QT; qq += 8) {
        const float inv = sinv[qq];
        for (int j = lane; j < 160; j += 32)
            Ps[qq * 168 + j] = __float2half_rn(j < jmax ? S[qq][j] * inv : 0.f);
    }
    __syncthreads();

    const int nb_w = warp * 8;
    for (int dc = 0; dc < 16; dc++) {
#pragma unroll
        for (int it = 0; it < 10; it++) {
            const int idx = tid + it * 256;
            const int row = idx >> 4;
            const int dg  = idx & 15;
            uint2 o = make_uint2(0u, 0u);
            if (row < jmax)
                o = *reinterpret_cast<const uint2*>(
                    qkv + base_bh + (size_t)row * 12288 + 8192 + dc * 64 + dg * 4);
            *reinterpret_cast<uint2*>(&Ks[row * 72 + dg * 4]) = o;
        }
        __syncthreads();

        float c[4] = {0.f, 0.f, 0.f, 0.f};
#pragma unroll
        for (int kt = 0; kt < 10; kt++) {
            const int kk = kt * 16;
            uint32_t a0 = ldh2(&Ps[(g    ) * 168 + kk + ac * 2    ]);
            uint32_t a1 = ldh2(&Ps[(g + 8) * 168 + kk + ac * 2    ]);
            uint32_t a2 = ldh2(&Ps[(g    ) * 168 + kk + ac * 2 + 8]);
            uint32_t a3 = ldh2(&Ps[(g + 8) * 168 + kk + ac * 2 + 8]);
            uint32_t b0, b1;
            ldsm_x2_trans(b0, b1,
                          smem_u32(&Ks[(kk + (lane & 15)) * 72 + nb_w]));
            mma_f16(c, a0, a1, a2, a3, b0, b1);
        }

        const int r0 = i0 + g;
        const int r1 = i0 + g + 8;
        const int dcol = dc * 64 + nb_w + ac * 2;
        if (r0 < SEQT) {
            __half2 hh = __floats2half2_rn(c[0], c[1]);
            *reinterpret_cast<uint32_t*>(
                out + (size_t)(b * SEQT + r0) * INNERC + (size_t)h * 1024 + dcol) =
                *reinterpret_cast<uint32_t*>(&hh);
        }
        if (r1 < SEQT) {
            __half2 hh = __floats2half2_rn(c[2], c[3]);
            *reinterpret_cast<uint32_t*>(
                out + (size_t)(b * SEQT + r1) * INNERC + (size_t)h * 1024 + dcol) =
                *reinterpret_cast<uint32_t*>(&hh);
        }
        __syncthreads();
    }
}

// ---------------------------------------------------------------------------
extern "C" void kernel_launch(void* const* d_in, const int* in_sizes, int n_in,
                              void* d_out, int out_size)
{
    const float* features    = (const float*)d_in[0];
    const float* mnorm_w     = (const float*)d_in[1];
    const float* mnorm_b     = (const float*)d_in[2];
    const float* in_proj_w   = (const float*)d_in[3];
    const float* conv_w      = (const float*)d_in[4];
    const float* conv_b      = (const float*)d_in[5];
    const float* x_proj_w    = (const float*)d_in[6];
    const float* dt_proj_w   = (const float*)d_in[7];
    const float* dt_proj_b   = (const float*)d_in[8];
    const float* A_log       = (const float*)d_in[9];
    const float* D_skip      = (const float*)d_in[10];
    const float* mamba_out_w = (const float*)d_in[11];
    const float* ln1_w       = (const float*)d_in[12];
    const float* ln1_b       = (const float*)d_in[13];
    const float* qkv_w       = (const float*)d_in[14];
    const float* attn_out_w  = (const float*)d_in[15];
    const float* attn_out_b  = (const float*)d_in[16];
    const float* ln2_w       = (const float*)d_in[17];
    const float* ln2_b       = (const float*)d_in[18];
    const float* ffn_w1      = (const float*)d_in[19];
    const float* ffn_b1      = (const float*)d_in[20];
    const float* ffn_w2      = (const float*)d_in[21];
    const float* ffn_b2      = (const float*)d_in[22];

    float  *p_xc, *p_xdbl, *p_xpart, *p_part2;
    __half *p_normh, *p_xzh, *p_xch, *p_xdbl16, *p_dth, *p_yh, *p_qkvh, *p_attnh, *p_ffnh;
    __half *w_inproj, *w_xproj, *w_dt, *w_mamba, *w_qkv, *w_attn, *w_ffn1, *w_ffn2;
    cudaGetSymbolAddress((void**)&p_normh,  g_normh);
    cudaGetSymbolAddress((void**)&p_xzh,    g_xzh);
    cudaGetSymbolAddress((void**)&p_xc,     g_xc);
    cudaGetSymbolAddress((void**)&p_xch,    g_xch);
    cudaGetSymbolAddress((void**)&p_xdbl,   g_xdbl);
    cudaGetSymbolAddress((void**)&p_xdbl16, g_xdbl16);
    cudaGetSymbolAddress((void**)&p_xpart,  g_xpart);
    cudaGetSymbolAddress((void**)&p_dth,    g_dth);
    cudaGetSymbolAddress((void**)&p_yh,     g_yh);
    cudaGetSymbolAddress((void**)&p_qkvh,   g_qkvh);
    cudaGetSymbolAddress((void**)&p_attnh,  g_attnh);
    cudaGetSymbolAddress((void**)&p_ffnh,   g_ffnh);
    cudaGetSymbolAddress((void**)&p_part2,  g_part2);
    cudaGetSymbolAddress((void**)&w_inproj, g_w_inproj);
    cudaGetSymbolAddress((void**)&w_xproj,  g_w_xproj);
    cudaGetSymbolAddress((void**)&w_dt,     g_w_dt);
    cudaGetSymbolAddress((void**)&w_mamba,  g_w_mamba);
    cudaGetSymbolAddress((void**)&w_qkv,    g_w_qkv);
    cudaGetSymbolAddress((void**)&w_attn,   g_w_attn);
    cudaGetSymbolAddress((void**)&w_ffn1,   g_w_ffn1);
    cudaGetSymbolAddress((void**)&w_ffn2,   g_w_ffn2);

    const int SMH  = 4 * (64 + 128) * 40 * 2;   // 61440 (BN=128)
    const int SMH2 = 4 * (64 + 256) * 40 * 2;   // 102400 (BN=256)
    cudaFuncSetAttribute((gemm_h<1, 1, 256>), cudaFuncAttributeMaxDynamicSharedMemorySize, SMH2);
    cudaFuncSetAttribute((gemm_h<2, 1, 256>), cudaFuncAttributeMaxDynamicSharedMemorySize, SMH2);
    cudaFuncSetAttribute((gemm_h<0, SKR, 256>), cudaFuncAttributeMaxDynamicSharedMemorySize, SMH2);
    cudaFuncSetAttribute((gemm_h<6, 1, 128>), cudaFuncAttributeMaxDynamicSharedMemorySize, SMH);
    cudaFuncSetAttribute((gemm_h<0, XKS, 128>), cudaFuncAttributeMaxDynamicSharedMemorySize, SMH);

    // ---- weight conversion ----
    auto conv16 = [&](const float* src, __half* dst, size_t n) {
        const int n4 = (int)(n / 4);
        f32to16<<<(n4 + 255) / 256, 256>>>(src, dst, n4);
    };
    conv16(in_proj_w,   w_inproj, (size_t)DEPTHC * 4096 * DIMC);
    conv16(x_proj_w,    w_xproj,  (size_t)DEPTHC * XDBLC * DINC);
    conv16(dt_proj_w,   w_dt,     (size_t)DEPTHC * DINC * DTRANK);
    conv16(mamba_out_w, w_mamba,  (size_t)DEPTHC * DIMC * DINC);
    conv16(qkv_w,       w_qkv,    (size_t)DEPTHC * 3 * INNERC * DIMC);
    conv16(attn_out_w,  w_attn,   (size_t)DEPTHC * DIMC * INNERC);
    conv16(ffn_w1,      w_ffn1,   (size_t)DEPTHC * MLPC * DIMC);
    conv16(ffn_w2,      w_ffn2,   (size_t)DEPTHC * DIMC * MLPC);

    float* X = (float*)d_out;
    cudaMemcpyAsync(X, features, sizeof(float) * (size_t)MTOT * DIMC,
                    cudaMemcpyDeviceToDevice);

    ln_kernel<<<MTOT, 256>>>(X, mnorm_w, mnorm_b, p_normh);

    for (int i = 0; i < DEPTHC; i++) {
        // ---- Mamba ----
        gemm_h<1, 1, 256><<<dim3(16, 19), 256, SMH2>>>(p_normh, DIMC,
                w_inproj + (size_t)i * 4096 * DIMC, DIMC,
                nullptr, p_xzh, 4096, MTOT, 4096, DIMC);
        conv_kernel<<<dim3(MTOT, 8), 256>>>(p_xzh, conv_w + (size_t)i * DINC * 4,
                                            conv_b + i * DINC, p_xc, p_xch);
        gemm_h<0, XKS, 128><<<dim3(1, 19, XKS), 256, SMH>>>(p_xch, DINC,
                w_xproj + (size_t)i * XDBLC * DINC, DINC,
                nullptr, p_xpart, XDBLC, MTOT, XDBLC, DINC);
        xproj_reduce<<<(MTOT * XDBLC + 255) / 256, 256>>>(p_xpart, p_xdbl, p_xdbl16);
        gemm_h<6, 1, 128><<<dim3(16, 19), 256, SMH>>>(p_xdbl16, XDBLC,
                w_dt + (size_t)i * DINC * DTRANK, DTRANK,
                dt_proj_b + i * DINC, p_dth, DINC, MTOT, DINC, DTRANK);
        scan_kernel<<<dim3(128, BATCH), 256>>>(p_dth, p_xc, p_xdbl,
                A_log + (size_t)i * DINC * DSTATE,
                D_skip + i * DINC, p_xzh, p_yh);
        gemm_h<0, SKR, 256><<<dim3(4, 19, SKR), 256, SMH2>>>(p_yh, DINC,
                w_mamba + (size_t)i * DIMC * DINC, DINC,
                nullptr, p_part2, DIMC, MTOT, DIMC, DINC);
        reduce_ln<3, true><<<MTOT, 256>>>(p_part2, nullptr, X,
                ln1_w + i * DIMC, ln1_b + i * DIMC, p_normh);

        // ---- Attention ----
        gemm_h<1, 1, 256><<<dim3(48, 19), 256, SMH2>>>(p_normh, DIMC,
                w_qkv + (size_t)i * 3 * INNERC * DIMC, DIMC,
                nullptr, p_qkvh, 3 * INNERC, MTOT, 3 * INNERC, DIMC);
        attn_tile_kernel<<<dim3(10, 4, BATCH), 256>>>(p_qkvh, p_attnh);
        gemm_h<0, SKR, 256><<<dim3(4, 19, SKR), 256, SMH2>>>(p_attnh, INNERC,
                w_attn + (size_t)i * DIMC * INNERC, INNERC,
                nullptr, p_part2, DIMC, MTOT, DIMC, INNERC);
        reduce_ln<4, true><<<MTOT, 256>>>(p_part2, attn_out_b + i * DIMC, X,
                ln2_w + i * DIMC, ln2_b + i * DIMC, p_normh);

        // ---- FFN ----
        gemm_h<2, 1, 256><<<dim3(16, 19), 256, SMH2>>>(p_normh, DIMC,
                w_ffn1 + (size_t)i * MLPC * DIMC, DIMC,
                ffn_b1 + i * MLPC, p_ffnh, MLPC, MTOT, MLPC, DIMC);
        gemm_h<0, SKR, 256><<<dim3(4, 19, SKR), 256, SMH2>>>(p_ffnh, MLPC,
                w_ffn2 + (size_t)i * DIMC * MLPC, MLPC,
                nullptr, p_part2, DIMC, MTOT, DIMC, MLPC);
        if (i + 1 < DEPTHC)
            reduce_ln<3, true><<<MTOT, 256>>>(p_part2, ffn_b2 + i * DIMC, X,
                    mnorm_w + (i + 1) * DIMC, mnorm_b + (i + 1) * DIMC, p_normh);
        else
            reduce_ln<3, false><<<MTOT, 256>>>(p_part2, ffn_b2 + i * DIMC, X,
                    nullptr, nullptr, nullptr);
    }
}